// round 4
// baseline (speedup 1.0000x reference)
#include <cuda_runtime.h>
#include <cstdint>
#include <cstddef>

#define DIM      900
#define TLEN     31000
#define DISCARD  1000
#define OUTCOLS  29999      /* TLEN - DISCARD - 1 */
#define NCTA     90
#define RPC      10         /* rows per CTA */
#define NTHREADS 160        /* 5 warps, 2 rows per warp */
#define PADDIM   1024       /* padded x length: 8 chunks of 128 */

// Ping-pong global state broadcast + monotonic arrival counter.
// Zero-initialized at module load. ctr only grows (90 arrivals per step), so
// graph replays need no reset: each launch recovers its base by rounding its
// first read down to a multiple of NCTA (at most 89 step-0 arrivals can
// precede any CTA's base read, since step-1 arrivals require all 90 step-0s).
// Pad region [900,1024) of g_x is never written -> stays zero; W registers for
// cols >= 900 are zeroed anyway.
__device__ __align__(16) float g_x[2][PADDIM];
__device__ unsigned long long g_ctr;

__device__ __forceinline__ unsigned long long ld_acq(const unsigned long long* p) {
    unsigned long long v;
    asm volatile("ld.acquire.gpu.global.b64 %0, [%1];" : "=l"(v) : "l"(p) : "memory");
    return v;
}
__device__ __forceinline__ void red_rel_add1(unsigned long long* p) {
    asm volatile("red.release.gpu.global.add.u64 [%0], 1;" :: "l"(p) : "memory");
}
// 16B L2 load as two packed fp32x2 words (feeds FFMA2 directly).
__device__ __forceinline__ ulonglong2 ld_cg16(const float* p) {
    ulonglong2 v;
    asm volatile("ld.global.cg.v2.b64 {%0,%1}, [%2];"
                 : "=l"(v.x), "=l"(v.y) : "l"(p) : "memory");
    return v;
}
__device__ __forceinline__ void st_cg2(float* p, float a, float b) {
    asm volatile("st.global.cg.v2.f32 [%0], {%1,%2};" :: "l"(p), "f"(a), "f"(b) : "memory");
}
__device__ __forceinline__ unsigned long long pk2(float a, float b) {
    unsigned long long r;
    asm("mov.b64 %0, {%1,%2};" : "=l"(r) : "f"(a), "f"(b));
    return r;
}
// Packed dual fp32 FMA (B300 FFMA2) — exact fp32 semantics, 2 MACs/instr.
__device__ __forceinline__ void fma2(unsigned long long& acc,
                                     unsigned long long a, unsigned long long b) {
    asm("fma.rn.f32x2 %0, %1, %2, %0;" : "+l"(acc) : "l"(a), "l"(b));
}
__device__ __forceinline__ float sum2(unsigned long long a) {
    float lo, hi;
    asm("mov.b64 {%0,%1}, %2;" : "=f"(lo), "=f"(hi) : "l"(a));
    return lo + hi;
}

__global__ void __launch_bounds__(NTHREADS, 1) esn_persistent(
    const float* __restrict__ W,     // (900, 900) row-major, symmetric
    const float* __restrict__ Win,   // (900, 900) row-major; column 0 used
    const float* __restrict__ u,     // (31000,)
    float* __restrict__ out)         // (900, 29999) row-major
{
    __shared__ unsigned long long s_base;

    const int tid  = threadIdx.x;
    const int cta  = blockIdx.x;
    const int warp = tid >> 5;
    const int lane = tid & 31;

    if (tid == 0) {
        unsigned long long o = ld_acq(&g_ctr);
        s_base = o - (o % (unsigned long long)NCTA);
    }

    // ---- This warp's 2 rows of W into registers, pre-scaled by 0.9 ----
    unsigned long long w0p[8][2], w1p[8][2];
    const int r0 = cta * RPC + warp * 2;
    #pragma unroll
    for (int k = 0; k < 8; ++k) {
        const int col = k * 128 + lane * 4;
        float a0 = 0.f, a1 = 0.f, a2 = 0.f, a3 = 0.f;
        float b0 = 0.f, b1 = 0.f, b2 = 0.f, b3 = 0.f;
        if (col + 3 < DIM) {
            float4 va = *(const float4*)(W + (size_t)r0 * DIM + col);
            float4 vb = *(const float4*)(W + (size_t)(r0 + 1) * DIM + col);
            a0 = va.x; a1 = va.y; a2 = va.z; a3 = va.w;
            b0 = vb.x; b1 = vb.y; b2 = vb.z; b3 = vb.w;
        }
        const float sr = 0.9f;  // reference: w_eff = 0.9*W elementwise
        w0p[k][0] = pk2(sr * a0, sr * a1);
        w0p[k][1] = pk2(sr * a2, sr * a3);
        w1p[k][0] = pk2(sr * b0, sr * b1);
        w1p[k][1] = pk2(sr * b2, sr * b3);
    }
    const float winA = Win[(size_t)r0 * DIM];          // W_in[r0, 0]
    const float winB = Win[(size_t)(r0 + 1) * DIM];    // W_in[r0+1, 0]

    __syncthreads();
    const unsigned long long base = s_base;

    // Lanes 0-15 track row r0's state; lanes 16-31 track row r0+1's.
    float xold = 0.0f;

    for (int s = 0; s < TLEN; ++s) {
        const float u_s = __ldg(u + s);   // L1 hit, overlaps everything

        unsigned long long a0 = 0, a1 = 0, a2 = 0, a3 = 0;
        if (s > 0) {
            // --- every warp spins itself (warp-uniform acquire load) ---
            const unsigned long long tgt =
                base + (unsigned long long)NCTA * (unsigned long long)s;
            while (ld_acq(&g_ctr) < tgt) { }

            // --- x_{s-1}: straight from L2 into FFMA2, no smem stage ---
            const float* xb = g_x[(s - 1) & 1] + lane * 4;
            #pragma unroll
            for (int k = 0; k < 8; ++k) {
                ulonglong2 xv = ld_cg16(xb + k * 128);
                fma2(a0, w0p[k][0], xv.x);
                fma2(a1, w0p[k][1], xv.y);
                fma2(a2, w1p[k][0], xv.x);
                fma2(a3, w1p[k][1], xv.y);
            }
        }
        const float sA = sum2(a0) + sum2(a1);   // partial of row r0
        const float sB = sum2(a2) + sum2(a3);   // partial of row r0+1

        // Merged 5-deep reduce: lanes 0-15 end with full sA, 16-31 with full sB.
        float v = (lane < 16) ? sA : sB;
        const float o = (lane < 16) ? sB : sA;
        v += __shfl_xor_sync(0xffffffffu, o, 16);
        v += __shfl_xor_sync(0xffffffffu, v, 8);
        v += __shfl_xor_sync(0xffffffffu, v, 4);
        v += __shfl_xor_sync(0xffffffffu, v, 2);
        v += __shfl_xor_sync(0xffffffffu, v, 1);

        const float wv = (lane < 16) ? winA : winB;
        const float xn = 0.3f * xold + 0.7f * tanhf(v + wv * u_s);
        xold = xn;

        if (lane == 0) {
            const float xn1 = __shfl_sync(0x00010001u, xn, 16);
            st_cg2(&g_x[s & 1][r0], xn, xn1);    // publish both rows
        } else if (lane == 16) {
            (void)__shfl_sync(0x00010001u, xn, 16);
        }

        __syncthreads();                         // all 5 warps published
        if (tid == 0) red_rel_add1(&g_ctr);      // release-arrive

        // Output stores AFTER the release — off the inter-CTA critical path.
        if (s > DISCARD) {
            const int t = s - (DISCARD + 1);
            if (lane == 0)  out[(size_t)r0 * OUTCOLS + t]       = xn;
            if (lane == 16) out[(size_t)(r0 + 1) * OUTCOLS + t] = xn;
        }
    }
}

extern "C" void kernel_launch(void* const* d_in, const int* in_sizes, int n_in,
                              void* d_out, int out_size) {
    const float* W   = (const float*)d_in[0];
    const float* Win = (const float*)d_in[1];
    const float* u   = (const float*)d_in[2];
    esn_persistent<<<NCTA, NTHREADS>>>(W, Win, u, (float*)d_out);
}

// round 5
// speedup vs baseline: 1.0259x; 1.0259x over previous
#include <cuda_runtime.h>
#include <cstdint>
#include <cstddef>

#define DIM      900
#define TLEN     31000
#define DISCARD  1000
#define OUTCOLS  29999      /* TLEN - DISCARD - 1 */
#define NCTA     30
#define RPC      30         /* rows per CTA */
#define NTHREADS 256        /* 8 warps; warps 0-6: 4 rows, warp 7: 2 rows */
#define PADDIM   1024       /* padded x length: 8 chunks of 128 */
#define FSTRIDE  32         /* flag stride in u32 = 128B -> one L2 line each */

// Ping-pong state broadcast + per-CTA release flags (NO atomics, no hot word).
// Flags are monotonically increasing step counts; each CTA writes only its own
// flag (128B apart -> distinct L2 lines/slices). Graph replays need no reset:
// every launch advances each flag by exactly TLEN, and each CTA reads its own
// flag (before writing it) to recover the launch base.
__device__ __align__(16) float g_x[2][PADDIM];
__device__ unsigned g_flags[NCTA * FSTRIDE];

__device__ __forceinline__ unsigned ld_acq32(const unsigned* p) {
    unsigned v;
    asm volatile("ld.acquire.gpu.global.u32 %0, [%1];" : "=r"(v) : "l"(p) : "memory");
    return v;
}
__device__ __forceinline__ void st_rel32(unsigned* p, unsigned v) {
    asm volatile("st.release.gpu.global.u32 [%0], %1;" :: "l"(p), "r"(v) : "memory");
}
// 16B L2 load as two packed fp32x2 words (feeds FFMA2 directly).
__device__ __forceinline__ ulonglong2 ld_cg16(const float* p) {
    ulonglong2 v;
    asm volatile("ld.global.cg.v2.b64 {%0,%1}, [%2];"
                 : "=l"(v.x), "=l"(v.y) : "l"(p) : "memory");
    return v;
}
__device__ __forceinline__ void st_cg2(float* p, float a, float b) {
    asm volatile("st.global.cg.v2.f32 [%0], {%1,%2};" :: "l"(p), "f"(a), "f"(b) : "memory");
}
__device__ __forceinline__ unsigned long long pk2(float a, float b) {
    unsigned long long r;
    asm("mov.b64 %0, {%1,%2};" : "=l"(r) : "f"(a), "f"(b));
    return r;
}
// Packed dual fp32 FMA (B300 FFMA2) — exact fp32 semantics, 2 MACs/instr.
__device__ __forceinline__ void fma2(unsigned long long& acc,
                                     unsigned long long a, unsigned long long b) {
    asm("fma.rn.f32x2 %0, %1, %2, %0;" : "+l"(acc) : "l"(a), "l"(b));
}
__device__ __forceinline__ float sum2(unsigned long long a) {
    float lo, hi;
    asm("mov.b64 {%0,%1}, %2;" : "=f"(lo), "=f"(hi) : "l"(a));
    return lo + hi;
}

__global__ void __launch_bounds__(NTHREADS, 1) esn_persistent(
    const float* __restrict__ W,     // (900, 900) row-major, symmetric
    const float* __restrict__ Win,   // (900, 900) row-major; column 0 used
    const float* __restrict__ u,     // (31000,)
    float* __restrict__ out)         // (900, 29999) row-major
{
    __shared__ unsigned s_base;

    const int tid  = threadIdx.x;
    const int cta  = blockIdx.x;
    const int warp = tid >> 5;
    const int lane = tid & 31;

    // Launch base from OUR OWN flag (read strictly before we ever write it).
    if (tid == 0) s_base = ld_acq32(&g_flags[cta * FSTRIDE]);

    // ---- This warp's 4 rows of W into registers, pre-scaled by 0.9 ----
    // wp[g][k][h]: row rbase+g, k-th 128-col chunk, h selects cols {0,1}/{2,3}.
    const int rbase = cta * RPC + warp * 4;
    unsigned long long wp[4][8][2];
    #pragma unroll
    for (int g = 0; g < 4; ++g) {
        const bool vg = (warp * 4 + g) < RPC;   // warp 7 has only 2 valid rows
        #pragma unroll
        for (int k = 0; k < 8; ++k) {
            const int col = k * 128 + lane * 4;
            float a0 = 0.f, a1 = 0.f, a2 = 0.f, a3 = 0.f;
            if (vg && col + 3 < DIM) {
                float4 v = *(const float4*)(W + (size_t)(rbase + g) * DIM + col);
                a0 = v.x; a1 = v.y; a2 = v.z; a3 = v.w;
            }
            wp[g][k][0] = pk2(0.9f * a0, 0.9f * a1);
            wp[g][k][1] = pk2(0.9f * a2, 0.9f * a3);
        }
    }
    // Lane group g = lane>>3 tracks row rbase+g.
    const int  myg   = lane >> 3;
    const bool vrow  = (warp * 4 + myg) < RPC;
    const int  myrow = rbase + myg;
    const float winv = vrow ? Win[(size_t)myrow * DIM] : 0.0f;   // W_in[row, 0]

    __syncthreads();
    const unsigned base = s_base;
    float xold = 0.0f;

    for (int s = 0; s < TLEN; ++s) {
        const float u_s = __ldg(u + s);   // L1 hit, overlaps the wait

        if (s > 0) {
            // --- warp 0 polls all 30 flags (one lane each, scalar acquire) ---
            if (warp == 0) {
                const unsigned tgt = base + (unsigned)s;
                for (;;) {
                    unsigned f = (lane < NCTA) ? ld_acq32(&g_flags[lane * FSTRIDE])
                                               : tgt;
                    if (__all_sync(0xffffffffu, (int)(f - tgt) >= 0)) break;
                }
            }
            __syncthreads();   // releases warps 1-7; orders via warp0's acquires
        }

        // ---- 4 rows: x_{s-1} straight from L2 into FFMA2 ----
        unsigned long long acc[4][2] = {};
        if (s > 0) {
            const float* xb = g_x[(s - 1) & 1] + lane * 4;
            #pragma unroll
            for (int k = 0; k < 8; ++k) {
                ulonglong2 xv = ld_cg16(xb + k * 128);
                #pragma unroll
                for (int g = 0; g < 4; ++g) {
                    fma2(acc[g][0], wp[g][k][0], xv.x);
                    fma2(acc[g][1], wp[g][k][1], xv.y);
                }
            }
        }
        float s0 = sum2(acc[0][0]) + sum2(acc[0][1]);
        float s1 = sum2(acc[1][0]) + sum2(acc[1][1]);
        float s2 = sum2(acc[2][0]) + sum2(acc[2][1]);
        float s3 = sum2(acc[3][0]) + sum2(acc[3][1]);

        // Grouped xor-fold: lanes 0-7 end with row0 sum, 8-15 row1,
        // 16-23 row2, 24-31 row3. 6 shfls total.
        float a = (lane & 16) ? s2 : s0;
        float b = (lane & 16) ? s0 : s2;
        a += __shfl_xor_sync(0xffffffffu, b, 16);
        float c = (lane & 16) ? s3 : s1;
        float d = (lane & 16) ? s1 : s3;
        c += __shfl_xor_sync(0xffffffffu, d, 16);
        float e = (lane & 8) ? c : a;
        float f = (lane & 8) ? a : c;
        e += __shfl_xor_sync(0xffffffffu, f, 8);
        e += __shfl_xor_sync(0xffffffffu, e, 4);
        e += __shfl_xor_sync(0xffffffffu, e, 2);
        e += __shfl_xor_sync(0xffffffffu, e, 1);

        const float xn = 0.3f * xold + 0.7f * tanhf(e + winv * u_s);
        xold = xn;

        // Gather the 4 row values to lane 0 and publish (2x 8B stores; rbase
        // is always even so both are 8B-aligned).
        const float v1 = __shfl_sync(0xffffffffu, xn, 8);
        const float v2 = __shfl_sync(0xffffffffu, xn, 16);
        const float v3 = __shfl_sync(0xffffffffu, xn, 24);
        if (lane == 0) {
            float* dst = &g_x[s & 1][rbase];
            st_cg2(dst, xn, v1);
            if (warp < 7) st_cg2(dst + 2, v2, v3);   // warp 7: rows 28,29 only
        }

        __syncthreads();   // all warps' x stores precede the release
        if (tid == 0) st_rel32(&g_flags[cta * FSTRIDE], base + (unsigned)s + 1u);

        // Output stores AFTER the release — off the inter-CTA critical path.
        if (s > DISCARD && vrow && (lane & 7) == 0) {
            out[(size_t)myrow * OUTCOLS + (s - (DISCARD + 1))] = xn;
        }
    }
}

extern "C" void kernel_launch(void* const* d_in, const int* in_sizes, int n_in,
                              void* d_out, int out_size) {
    const float* W   = (const float*)d_in[0];
    const float* Win = (const float*)d_in[1];
    const float* u   = (const float*)d_in[2];
    esn_persistent<<<NCTA, NTHREADS>>>(W, Win, u, (float*)d_out);
}

// round 7
// speedup vs baseline: 1.7843x; 1.7393x over previous
#include <cuda_runtime.h>
#include <cstdint>
#include <cstddef>

#define DIM      900
#define TLEN     31000
#define DISCARD  1000
#define OUTCOLS  29999      /* TLEN - DISCARD - 1 */
#define NCTA     30
#define RPC      30         /* rows per CTA */
#define NTHREADS 256        /* 8 warps; warps 0-6: 4 rows, warp 7: 2 rows */
#define PADDIM   1024

// Broadcast state: 900 self-verifying 8B words {f32 value (lo), u32 tag (hi)},
// ping-pong by step parity. 64-bit aligned stores are single-copy atomic, so a
// fresh tag ALWAYS travels with its fresh value — no fences, no flags needed.
// Lap safety: a row's tag on parity p advances +2 only after every CTA's poll
// warps consumed the previous tag on that parity (each CTA's bar1 couples all
// 8 chunks => all 900 rows). Tags grow monotonically across graph replays;
// base is recovered from g_xp[1][0] (the last parity written by a launch),
// and no CTA can overwrite that word before all CTAs have read it (overwrite
// at step 1 requires all step-0 publishes, each preceded by the base read).
__device__ unsigned long long g_xp[2][PADDIM];

__device__ __forceinline__ ulonglong2 ld_cv2(const unsigned long long* p) {
    ulonglong2 v;
    asm volatile("ld.global.cv.v2.b64 {%0,%1}, [%2];"
                 : "=l"(v.x), "=l"(v.y) : "l"(p) : "memory");
    return v;
}
__device__ __forceinline__ void st_cg64(unsigned long long* p, unsigned long long v) {
    asm volatile("st.global.cg.b64 [%0], %1;" :: "l"(p), "l"(v) : "memory");
}
__device__ __forceinline__ unsigned long long pk_pair(float v, unsigned tag) {
    unsigned long long r;
    asm("mov.b64 %0, {%1,%2};" : "=l"(r) : "r"(__float_as_uint(v)), "r"(tag));
    return r;
}
__device__ __forceinline__ void unpk(unsigned long long w, float& v, unsigned& t) {
    unsigned lo, hi;
    asm("mov.b64 {%0,%1}, %2;" : "=r"(lo), "=r"(hi) : "l"(w));
    v = __uint_as_float(lo); t = hi;
}
__device__ __forceinline__ unsigned long long pk2(float a, float b) {
    unsigned long long r;
    asm("mov.b64 %0, {%1,%2};" : "=l"(r) : "f"(a), "f"(b));
    return r;
}
// Packed dual fp32 FMA (B300 FFMA2) — exact fp32 semantics, 2 MACs/instr.
__device__ __forceinline__ void fma2(unsigned long long& acc,
                                     unsigned long long a, unsigned long long b) {
    asm("fma.rn.f32x2 %0, %1, %2, %0;" : "+l"(acc) : "l"(a), "l"(b));
}
__device__ __forceinline__ float sum2(unsigned long long a) {
    float lo, hi;
    asm("mov.b64 {%0,%1}, %2;" : "=f"(lo), "=f"(hi) : "l"(a));
    return lo + hi;
}
// Fast tanh: 1 - 2/(exp(2x)+1). MUFU-based; ~1e-7 abs error, handles +/-inf.
__device__ __forceinline__ float ftanh(float x) {
    float e = __expf(2.0f * x);
    return 1.0f - __fdividef(2.0f, e + 1.0f);
}

__global__ void __launch_bounds__(NTHREADS, 1) esn_persistent(
    const float* __restrict__ W,     // (900, 900) row-major, symmetric
    const float* __restrict__ Win,   // (900, 900) row-major; column 0 used
    const float* __restrict__ u,     // (31000,)
    float* __restrict__ out)         // (900, 29999) row-major
{
    __shared__ __align__(16) float x_sm[PADDIM];

    const int tid  = threadIdx.x;
    const int cta  = blockIdx.x;
    const int warp = tid >> 5;
    const int lane = tid & 31;

    // Zero x_sm; pad region [900,1024) stays zero forever.
    for (int i = tid; i < PADDIM; i += NTHREADS) x_sm[i] = 0.0f;

    // Launch base: tag of row 0, parity 1 (every launch's final write parity).
    unsigned base;
    { float dummy; unpk(ld_cv2(&g_xp[1][0]).x, dummy, base); }

    // ---- This warp's 4 rows of W into registers, pre-scaled by 0.9 ----
    const int rbase = cta * RPC + warp * 4;
    unsigned long long wp[4][8][2];
    #pragma unroll
    for (int g = 0; g < 4; ++g) {
        const bool vg = (warp * 4 + g) < RPC;   // warp 7: 2 valid rows
        #pragma unroll
        for (int k = 0; k < 8; ++k) {
            const int col = k * 128 + lane * 4;
            float a0 = 0.f, a1 = 0.f, a2 = 0.f, a3 = 0.f;
            if (vg && col + 3 < DIM) {
                float4 v = *(const float4*)(W + (size_t)(rbase + g) * DIM + col);
                a0 = v.x; a1 = v.y; a2 = v.z; a3 = v.w;
            }
            wp[g][k][0] = pk2(0.9f * a0, 0.9f * a1);
            wp[g][k][1] = pk2(0.9f * a2, 0.9f * a3);
        }
    }
    const int  myg   = lane >> 3;
    const bool vrow  = (warp * 4 + myg) < RPC;
    const int  myrow = rbase + myg;
    const float winv = vrow ? Win[(size_t)myrow * DIM] : 0.0f;   // W_in[row,0]

    // This warp's poll chunk: pairs [warp*128 + lane*4, +4). Chunk 7 has only
    // 4 valid pairs (lane 0: cols 896-899); inactive lanes contribute ok=true
    // inside the SAME convergent loop (single __all_sync call site -- the
    // divergent two-loop version deadlocks under independent thread sched).
    const int  cidx    = warp * 128 + lane * 4;
    const bool pactive = cidx < DIM;
    const unsigned long long* const pb0 = &g_xp[0][pactive ? cidx : 0];
    const unsigned long long* const pb1 = &g_xp[1][pactive ? cidx : 0];

    __syncthreads();
    float xold = 0.0f;

    for (int s = 0; s < TLEN; ++s) {
        const float u_s = __ldg(u + s);

        // ---- poll own chunk: tag+data arrive in the same loads ----
        if (s > 0) {
            const unsigned tgt = base + (unsigned)s;
            const unsigned long long* pb = ((s - 1) & 1) ? pb1 : pb0;
            float f0 = 0.f, f1 = 0.f, f2 = 0.f, f3 = 0.f;
            for (;;) {                       // ONE convergent loop, all lanes
                bool ok = true;
                if (pactive) {
                    ulonglong2 q0 = ld_cv2(pb);
                    ulonglong2 q1 = ld_cv2(pb + 2);
                    unsigned t0, t1, t2, t3;
                    unpk(q0.x, f0, t0); unpk(q0.y, f1, t1);
                    unpk(q1.x, f2, t2); unpk(q1.y, f3, t3);
                    ok = (t0 == tgt) & (t1 == tgt) & (t2 == tgt) & (t3 == tgt);
                }
                if (__all_sync(0xffffffffu, ok)) break;
            }
            if (pactive)
                *(float4*)(x_sm + cidx) = make_float4(f0, f1, f2, f3);
        }
        __syncthreads();   // bar1: x_{s-1} fully staged

        // ---- compute this warp's 4 rows from smem ----
        unsigned long long acc[4][2] = {};
        if (s > 0) {
            #pragma unroll
            for (int k = 0; k < 8; ++k) {
                ulonglong2 xv = *(const ulonglong2*)(x_sm + k * 128 + lane * 4);
                #pragma unroll
                for (int g = 0; g < 4; ++g) {
                    fma2(acc[g][0], wp[g][k][0], xv.x);
                    fma2(acc[g][1], wp[g][k][1], xv.y);
                }
            }
        }
        float s0 = sum2(acc[0][0]) + sum2(acc[0][1]);
        float s1 = sum2(acc[1][0]) + sum2(acc[1][1]);
        float s2 = sum2(acc[2][0]) + sum2(acc[2][1]);
        float s3 = sum2(acc[3][0]) + sum2(acc[3][1]);

        // Grouped xor-fold: lanes 0-7 -> row0 sum, 8-15 -> row1,
        // 16-23 -> row2, 24-31 -> row3. 6 shfls.
        float a = (lane & 16) ? s2 : s0;
        float b = (lane & 16) ? s0 : s2;
        a += __shfl_xor_sync(0xffffffffu, b, 16);
        float c = (lane & 16) ? s3 : s1;
        float d = (lane & 16) ? s1 : s3;
        c += __shfl_xor_sync(0xffffffffu, d, 16);
        float e = (lane & 8) ? c : a;
        float f = (lane & 8) ? a : c;
        e += __shfl_xor_sync(0xffffffffu, f, 8);
        e += __shfl_xor_sync(0xffffffffu, e, 4);
        e += __shfl_xor_sync(0xffffffffu, e, 2);
        e += __shfl_xor_sync(0xffffffffu, e, 1);

        const float xn = 0.3f * xold + 0.7f * ftanh(e + winv * u_s);
        xold = xn;

        // ---- publish: ONE atomic 8B {value, tag} store per row. No fence. ----
        if (vrow && (lane & 7) == 0) {
            st_cg64(&g_xp[s & 1][myrow], pk_pair(xn, base + (unsigned)s + 1u));
            if (s > DISCARD)
                out[(size_t)myrow * OUTCOLS + (s - (DISCARD + 1))] = xn;
        }

        __syncthreads();   // bar2: no warp re-stages x_sm while others read it
    }
}

extern "C" void kernel_launch(void* const* d_in, const int* in_sizes, int n_in,
                              void* d_out, int out_size) {
    const float* W   = (const float*)d_in[0];
    const float* Win = (const float*)d_in[1];
    const float* u   = (const float*)d_in[2];
    esn_persistent<<<NCTA, NTHREADS>>>(W, Win, u, (float*)d_out);
}